// round 4
// baseline (speedup 1.0000x reference)
#include <cuda_runtime.h>

// ---------------------------------------------------------------------------
// My_loss: masked sum over N of  |oP - tP| + 1.9*|V*drho_mix_dp(0.1*oP)*dpdt - mdot|
// Single persistent-grid kernel (one wave @ 6 blocks/SM), fused finish.
// R4: minimal-instruction math via bare approx MUFU ops (rcp/lg2/ex2).
// ---------------------------------------------------------------------------

#define TPB     256
#define BPSM    6
#define NBLOCKS (148 * BPSM)

__device__ double       g_acc    = 0.0;
__device__ unsigned int g_ticket = 0u;

__device__ __forceinline__ float f_rcp(float x) {
    float r; asm("rcp.approx.f32 %0, %1;" : "=f"(r) : "f"(x)); return r;
}
__device__ __forceinline__ float f_lg2(float x) {
    float r; asm("lg2.approx.f32 %0, %1;" : "=f"(r) : "f"(x)); return r;
}
__device__ __forceinline__ float f_ex2(float x) {
    float r; asm("ex2.approx.f32 %0, %1;" : "=f"(r) : "f"(x)); return r;
}

struct C10 {
    float patm, pmin, invL, sixInvL;
    float inv_poly, Ca, neg_exp, invBetaL, bgOverBL, rhoV;
};

__device__ __forceinline__ float loss_elem(float oP, float tP, float dp, float md,
                                           const C10& c)
{
    float pu  = fmaxf(0.1f * oP, c.pmin);
    float dpa = pu - c.patm;

    // smoothstep (clamped -> boundary cases exact)
    float x      = __saturatef(dpa * c.invL);
    float xx     = x * x;
    float theta  = fmaf(xx, fmaf(2.f, x, -3.f), 1.f);      // 1 + x^2(2x-3)
    float y      = xx - x;                                  // x(x-1)
    float dtheta = c.sixInvL * y;

    float rpu = f_rcp(pu);
    // pr = afr*(patm/pu)^(1/n) = Ca * 2^(-inv_poly * lg2(pu))
    float pr  = c.Ca * f_ex2(-c.inv_poly * f_lg2(pu));
    float p_denom = pr * theta;
    float t1  = theta * c.inv_poly;
    float p_ratio = pr * fmaf(t1, rpu, -dtheta);

    float base = fmaf(c.bgOverBL, dpa, 1.f);
    float g1   = f_ex2(c.neg_exp * f_lg2(base));            // base^(-1-1/bg)
    float exp_term = g1 * c.invBetaL;
    float denom    = fmaf(g1, base, p_denom);               // base^(-1/bg) + p_denom

    float rd  = f_rcp(denom);
    float t2  = (exp_term + p_ratio) * rd;
    float drho = c.rhoV * t2 * rd;                          // rhoV = V*(rhoL+rhoG*afr)

    float lp  = fabsf(fmaf(drho, dp, -md));
    float per = fmaf(1.9f, lp, fabsf(oP - tP));
    return (fabsf(dp) >= 1e-12f) ? per : 0.f;
}

__global__ void __launch_bounds__(TPB, BPSM)
k_loss(const float4* __restrict__ tP4, const float4* __restrict__ dp4,
       const float4* __restrict__ md4, const float4* __restrict__ oP4,
       const float* __restrict__ sV,
       const float* __restrict__ sRhoL, const float* __restrict__ sBetaL,
       const float* __restrict__ sBg,   const float* __restrict__ sAf,
       const float* __restrict__ sRhoG, const float* __restrict__ sPoly,
       const float* __restrict__ sPatm, const float* __restrict__ sPcrit,
       const float* __restrict__ sPmin, int n4, float* __restrict__ out)
{
    C10 c;
    {
        float patm  = __ldg(sPatm);
        float pcrit = __ldg(sPcrit);
        float af    = __ldg(sAf);
        float poly  = __ldg(sPoly);
        float bg    = __ldg(sBg);
        float betaL = __ldg(sBetaL);

        c.patm  = patm;
        c.pmin  = __ldg(sPmin);
        c.invL  = f_rcp(pcrit - patm);
        c.sixInvL = 6.f * c.invL;
        c.inv_poly = f_rcp(poly);
        float afr = af * f_rcp(1.f - af);
        c.Ca = afr * f_ex2(c.inv_poly * f_lg2(patm));
        c.neg_exp  = -1.f - f_rcp(bg);
        c.invBetaL = f_rcp(betaL);
        c.bgOverBL = bg * c.invBetaL;
        c.rhoV = (__ldg(sRhoL) + __ldg(sRhoG) * afr) * __ldg(sV);
    }

    float acc0 = 0.f, acc1 = 0.f;
    const int stride = gridDim.x * blockDim.x;
    for (int i = blockIdx.x * blockDim.x + threadIdx.x; i < n4; i += stride) {
        float4 o = oP4[i];
        float4 t = tP4[i];
        float4 d = dp4[i];
        float4 m = md4[i];
        acc0 += loss_elem(o.x, t.x, d.x, m.x, c);
        acc1 += loss_elem(o.y, t.y, d.y, m.y, c);
        acc0 += loss_elem(o.z, t.z, d.z, m.z, c);
        acc1 += loss_elem(o.w, t.w, d.w, m.w, c);
    }
    float acc = acc0 + acc1;

    // warp reduce (float), block reduce (double), global finish
    #pragma unroll
    for (int off = 16; off; off >>= 1)
        acc += __shfl_xor_sync(0xffffffffu, acc, off);

    __shared__ double s_warp[TPB / 32];
    if ((threadIdx.x & 31) == 0)
        s_warp[threadIdx.x >> 5] = (double)acc;
    __syncthreads();

    if (threadIdx.x == 0) {
        double b = 0.0;
        #pragma unroll
        for (int w = 0; w < TPB / 32; w++) b += s_warp[w];

        atomicAdd(&g_acc, b);
        __threadfence();
        unsigned int tkt = atomicAdd(&g_ticket, 1u);
        if (tkt == (unsigned int)(gridDim.x - 1)) {
            double total = *((volatile double*)&g_acc);
            *out = (float)total;
            *((volatile double*)&g_acc) = 0.0;
            __threadfence();
            *((volatile unsigned int*)&g_ticket) = 0u;
        }
    }
}

extern "C" void kernel_launch(void* const* d_in, const int* in_sizes, int n_in,
                              void* d_out, int out_size)
{
    const float4* tP4 = (const float4*)d_in[0];   // targets_P
    const float4* dp4 = (const float4*)d_in[1];   // dpdt
    const float4* md4 = (const float4*)d_in[2];   // mdot_A
    const float*  sV  = (const float*)d_in[3];    // V
    const float4* oP4 = (const float4*)d_in[4];   // outputs_P
    const float*  sRhoL  = (const float*)d_in[5];
    const float*  sBetaL = (const float*)d_in[6];
    const float*  sBg    = (const float*)d_in[7];
    const float*  sAf    = (const float*)d_in[8];
    const float*  sRhoG  = (const float*)d_in[9];
    const float*  sPoly  = (const float*)d_in[10];
    const float*  sPatm  = (const float*)d_in[11];
    const float*  sPcrit = (const float*)d_in[12];
    const float*  sPmin  = (const float*)d_in[13];

    int n  = in_sizes[0];
    int n4 = n / 4;   // N = 8,000,000 divisible by 4

    k_loss<<<NBLOCKS, TPB>>>(tP4, dp4, md4, oP4, sV, sRhoL, sBetaL, sBg, sAf,
                             sRhoG, sPoly, sPatm, sPcrit, sPmin, n4,
                             (float*)d_out);
}

// round 5
// speedup vs baseline: 1.0601x; 1.0601x over previous
#include <cuda_runtime.h>

// ---------------------------------------------------------------------------
// My_loss: masked sum over N of  |oP - tP| + 1.9*|V*drho_mix_dp(0.1*oP)*dpdt - mdot|
// Single persistent-grid kernel (one wave @ 6 blocks/SM), fused finish.
// R5: R3 math (intrinsics) + unroll-by-2 front-batched loads (MLP_p1=8) + __ldcs.
// ---------------------------------------------------------------------------

#define TPB     256
#define BPSM    6
#define NBLOCKS (148 * BPSM)

__device__ double       g_acc    = 0.0;
__device__ unsigned int g_ticket = 0u;

struct C10 {
    float patm, pmin, invL, sixInvL;
    float inv_poly, Ca, neg_exp, invBetaL, bgOverBL, rhoV;
};

__device__ __forceinline__ float loss_elem(float oP, float tP, float dp, float md,
                                           const C10& c)
{
    float pu  = fmaxf(0.1f * oP, c.pmin);
    float dpa = pu - c.patm;

    // branch-free smoothstep: clamp makes boundary cases exact
    float x      = __saturatef(dpa * c.invL);
    float xx     = x * x;
    float theta  = fmaf(xx, fmaf(2.f, x, -3.f), 1.f);      // 1 + x^2(2x-3)
    float dtheta = c.sixInvL * (xx - x);                    // 6/L * x(x-1)

    float rpu = __fdividef(1.f, pu);
    float pr  = c.Ca * __powf(pu, -c.inv_poly);             // afr*(patm/pu)^(1/n)
    float p_denom = pr * theta;
    float p_ratio = pr * fmaf(theta * rpu, c.inv_poly, -dtheta);

    float base = fmaf(c.bgOverBL, dpa, 1.f);
    float g1   = __powf(base, c.neg_exp);                   // base^(-1-1/bg)
    float exp_term = g1 * c.invBetaL;
    float denom    = fmaf(g1, base, p_denom);               // base^(-1/bg) + p_denom

    float rd   = __fdividef(1.f, denom);
    float drho = c.rhoV * (exp_term + p_ratio) * rd * rd;   // rhoV includes V

    float lp  = fabsf(fmaf(drho, dp, -md));
    float per = fmaf(1.9f, lp, fabsf(oP - tP));
    return (fabsf(dp) >= 1e-12f) ? per : 0.f;
}

__device__ __forceinline__ float quad(const float4& o, const float4& t,
                                      const float4& d, const float4& m,
                                      const C10& c)
{
    float a0 = loss_elem(o.x, t.x, d.x, m.x, c);
    float a1 = loss_elem(o.y, t.y, d.y, m.y, c);
    float a2 = loss_elem(o.z, t.z, d.z, m.z, c);
    float a3 = loss_elem(o.w, t.w, d.w, m.w, c);
    return (a0 + a1) + (a2 + a3);
}

__global__ void __launch_bounds__(TPB, BPSM)
k_loss(const float4* __restrict__ tP4, const float4* __restrict__ dp4,
       const float4* __restrict__ md4, const float4* __restrict__ oP4,
       const float* __restrict__ sV,
       const float* __restrict__ sRhoL, const float* __restrict__ sBetaL,
       const float* __restrict__ sBg,   const float* __restrict__ sAf,
       const float* __restrict__ sRhoG, const float* __restrict__ sPoly,
       const float* __restrict__ sPatm, const float* __restrict__ sPcrit,
       const float* __restrict__ sPmin, int n4, float* __restrict__ out)
{
    C10 c;
    {
        float patm  = __ldg(sPatm);
        float pcrit = __ldg(sPcrit);
        float af    = __ldg(sAf);
        float poly  = __ldg(sPoly);
        float bg    = __ldg(sBg);
        float betaL = __ldg(sBetaL);

        c.patm  = patm;
        c.pmin  = __ldg(sPmin);
        c.invL  = __fdividef(1.f, pcrit - patm);
        c.sixInvL = 6.f * c.invL;
        c.inv_poly = __fdividef(1.f, poly);
        float afr = __fdividef(af, 1.f - af);
        c.Ca = afr * __powf(patm, c.inv_poly);
        c.neg_exp  = -1.f - __fdividef(1.f, bg);
        c.invBetaL = __fdividef(1.f, betaL);
        c.bgOverBL = bg * c.invBetaL;
        c.rhoV = (__ldg(sRhoL) + __ldg(sRhoG) * afr) * __ldg(sV);
    }

    float acc0 = 0.f, acc1 = 0.f;
    const int stride = gridDim.x * blockDim.x;
    int i = blockIdx.x * blockDim.x + threadIdx.x;

    // unroll-by-2: 8 front-batched streaming LDG.128 per iteration
    for (; i + stride < n4; i += 2 * stride) {
        int j = i + stride;
        float4 oA = __ldcs(oP4 + i);
        float4 tA = __ldcs(tP4 + i);
        float4 dA = __ldcs(dp4 + i);
        float4 mA = __ldcs(md4 + i);
        float4 oB = __ldcs(oP4 + j);
        float4 tB = __ldcs(tP4 + j);
        float4 dB = __ldcs(dp4 + j);
        float4 mB = __ldcs(md4 + j);
        acc0 += quad(oA, tA, dA, mA, c);
        acc1 += quad(oB, tB, dB, mB, c);
    }
    for (; i < n4; i += stride) {
        float4 o = __ldcs(oP4 + i);
        float4 t = __ldcs(tP4 + i);
        float4 d = __ldcs(dp4 + i);
        float4 m = __ldcs(md4 + i);
        acc0 += quad(o, t, d, m, c);
    }
    float acc = acc0 + acc1;

    // warp reduce (float), block reduce (double), global finish
    #pragma unroll
    for (int off = 16; off; off >>= 1)
        acc += __shfl_xor_sync(0xffffffffu, acc, off);

    __shared__ double s_warp[TPB / 32];
    if ((threadIdx.x & 31) == 0)
        s_warp[threadIdx.x >> 5] = (double)acc;
    __syncthreads();

    if (threadIdx.x == 0) {
        double b = 0.0;
        #pragma unroll
        for (int w = 0; w < TPB / 32; w++) b += s_warp[w];

        atomicAdd(&g_acc, b);
        __threadfence();
        unsigned int tkt = atomicAdd(&g_ticket, 1u);
        if (tkt == (unsigned int)(gridDim.x - 1)) {
            double total = *((volatile double*)&g_acc);
            *out = (float)total;
            *((volatile double*)&g_acc) = 0.0;
            __threadfence();
            *((volatile unsigned int*)&g_ticket) = 0u;
        }
    }
}

extern "C" void kernel_launch(void* const* d_in, const int* in_sizes, int n_in,
                              void* d_out, int out_size)
{
    const float4* tP4 = (const float4*)d_in[0];   // targets_P
    const float4* dp4 = (const float4*)d_in[1];   // dpdt
    const float4* md4 = (const float4*)d_in[2];   // mdot_A
    const float*  sV  = (const float*)d_in[3];    // V
    const float4* oP4 = (const float4*)d_in[4];   // outputs_P
    const float*  sRhoL  = (const float*)d_in[5];
    const float*  sBetaL = (const float*)d_in[6];
    const float*  sBg    = (const float*)d_in[7];
    const float*  sAf    = (const float*)d_in[8];
    const float*  sRhoG  = (const float*)d_in[9];
    const float*  sPoly  = (const float*)d_in[10];
    const float*  sPatm  = (const float*)d_in[11];
    const float*  sPcrit = (const float*)d_in[12];
    const float*  sPmin  = (const float*)d_in[13];

    int n  = in_sizes[0];
    int n4 = n / 4;   // N = 8,000,000 divisible by 4

    k_loss<<<NBLOCKS, TPB>>>(tP4, dp4, md4, oP4, sV, sRhoL, sBetaL, sBg, sAf,
                             sRhoG, sPoly, sPatm, sPcrit, sPmin, n4,
                             (float*)d_out);
}